// round 6
// baseline (speedup 1.0000x reference)
#include <cuda_runtime.h>

#define T_STEPS 2048
#define BATCH   256
#define HID     128
#define G3      384
#define NROW    384      // row threads (warps 0-11); update threads = 128 (warps 12-15)
#define KREG    96       // k's held in registers per row
#define KSM     32       // k's held in smem per row (k = 96..127)
#define WPAD2   36       // smem row stride (floats); stride 144B -> conflict-free LDS.128
#define NTHREADS 512
#define GH_STRIDE 392

typedef unsigned long long u64;

__device__ __forceinline__ u64 ffma2(u64 a, u64 b, u64 c) {
    u64 d;
    asm("fma.rn.f32x2 %0, %1, %2, %3;" : "=l"(d) : "l"(a), "l"(b), "l"(c));
    return d;
}
__device__ __forceinline__ float hsum2(u64 v) {
    float x, y;
    asm("mov.b64 {%0, %1}, %2;" : "=f"(x), "=f"(y) : "l"(v));
    return x + y;
}
#define BAR_SYNC(id)   asm volatile("bar.sync %0, %1;"   :: "r"(id), "r"(NTHREADS) : "memory")
#define BAR_ARRIVE(id) asm volatile("bar.arrive %0, %1;" :: "r"(id), "r"(NTHREADS) : "memory")

__global__ void __launch_bounds__(NTHREADS, 1)
gru_impute_kernel(const float* __restrict__ x,     // [B, T] (I=1)
                  const float* __restrict__ Wih,   // [384, 1]
                  const float* __restrict__ Whh,   // [384, 128]
                  const float* __restrict__ bih,   // [384]
                  const float* __restrict__ bhh,   // [384]
                  const float* __restrict__ Wfc,   // [1, 128]
                  const float* __restrict__ bfc,   // [1]
                  float* __restrict__ out)
{
    extern __shared__ float sm[];
    float* ws2   = sm;                       // NROW * WPAD2 (k=96..127 of each Whh row)
    float* ghs   = ws2  + NROW * WPAD2;      // 2 * GH_STRIDE gate pre-acts
    float* hs    = ghs  + 2 * GH_STRIDE;     // 2 * HID (16B aligned)
    float* xpart = hs   + 2 * HID;           // 2 * 4 warp partials of h.Wfc

    const int tid = threadIdx.x;
    const int b0  = blockIdx.x * 2;

    // ---- one-time staging ----
    for (int idx = tid; idx < NROW * KSM; idx += NTHREADS) {
        int r = idx >> 5, c = idx & 31;
        ws2[r * WPAD2 + c] = Whh[r * HID + KREG + c];
    }
    for (int idx = tid; idx < 2 * HID; idx += NTHREADS) hs[idx] = 0.0f;
    if (tid < 8) xpart[tid] = 0.0f;

    float* newin = out;                       // [T, B]
    float* pred  = out + T_STEPS * BATCH;     // [B, T-1]

    if (tid < NROW) {
        // ================= ROW THREADS (warps 0-11) =================
        u64 wr[KREG / 2];
        {
            const u64* wrow = reinterpret_cast<const u64*>(Whh + tid * HID);
            #pragma unroll
            for (int i = 0; i < KREG / 2; ++i) wr[i] = __ldg(wrow + i);
        }
        const float breg = bhh[tid];
        __syncthreads();

        const ulonglong2* wp  = reinterpret_cast<const ulonglong2*>(ws2 + tid * WPAD2);
        const ulonglong2* hp0 = reinterpret_cast<const ulonglong2*>(hs);
        const ulonglong2* hp1 = reinterpret_cast<const ulonglong2*>(hs + HID);

        for (int t = 0; t < T_STEPS; ++t) {
            if (t) BAR_SYNC(2);                      // h(b0,t-1) ready; ghs0 free
            {
                u64 a0 = 0ull, a1 = 0ull;
                #pragma unroll
                for (int j = 0; j < KREG / 4; ++j) {     // k = 0..95 from registers
                    ulonglong2 h = hp0[j];
                    a0 = ffma2(wr[2 * j],     h.x, a0);
                    a1 = ffma2(wr[2 * j + 1], h.y, a1);
                }
                #pragma unroll
                for (int j = 0; j < KSM / 4; ++j) {      // k = 96..127 from smem
                    ulonglong2 w = wp[j];
                    ulonglong2 h = hp0[KREG / 4 + j];
                    a0 = ffma2(w.x, h.x, a0);
                    a1 = ffma2(w.y, h.y, a1);
                }
                ghs[tid] = hsum2(a0) + hsum2(a1) + breg;
            }
            BAR_ARRIVE(1);                           // gh(b0,t) ready
            if (t) BAR_SYNC(4);                      // h(b1,t-1) ready; ghs1 free
            {
                u64 a0 = 0ull, a1 = 0ull;
                #pragma unroll
                for (int j = 0; j < KREG / 4; ++j) {
                    ulonglong2 h = hp1[j];
                    a0 = ffma2(wr[2 * j],     h.x, a0);
                    a1 = ffma2(wr[2 * j + 1], h.y, a1);
                }
                #pragma unroll
                for (int j = 0; j < KSM / 4; ++j) {
                    ulonglong2 w = wp[j];
                    ulonglong2 h = hp1[KREG / 4 + j];
                    a0 = ffma2(w.x, h.x, a0);
                    a1 = ffma2(w.y, h.y, a1);
                }
                ghs[GH_STRIDE + tid] = hsum2(a0) + hsum2(a1) + breg;
            }
            BAR_ARRIVE(3);                           // gh(b1,t) ready
        }
    } else {
        // ================= UPDATE THREADS (warps 12-15) =================
        const int u    = tid - NROW;          // 0..127
        const int lane = u & 31;
        const int wrp  = u >> 5;              // 0..3

        const float wih_r = Wih[u];        const float bih_r = bih[u];
        const float wih_z = Wih[u + 128];  const float bih_z = bih[u + 128];
        const float wih_n = Wih[u + 256];  const float bih_n = bih[u + 256];
        const float wfc   = Wfc[u];
        const float bf    = bfc[0];

        float h0 = 0.0f, h1 = 0.0f;           // h_old per batch, register-resident
        float x0n = __ldg(x + (size_t)b0 * T_STEPS);
        float x1n = __ldg(x + (size_t)(b0 + 1) * T_STEPS);
        __syncthreads();

        for (int t = 0; t < T_STEPS; ++t) {
            BAR_SYNC(1);                         // gh(b0,t) ready (also orders xpart)
            float xh0 = xpart[0] + xpart[1] + xpart[2] + xpart[3] + bf;
            float xh1 = xpart[4] + xpart[5] + xpart[6] + xpart[7] + bf;
            float x0 = x0n, x1 = x1n;
            if (t + 1 < T_STEPS) {               // prefetch next step's inputs
                x0n = __ldg(x + (size_t)b0 * T_STEPS + t + 1);
                x1n = __ldg(x + (size_t)(b0 + 1) * T_STEPS + t + 1);
            }
            // ---- batch b0 ----
            {
                float cur = (t == 0) ? x0 : ((x0 == 128.0f) ? xh0 : x0);
                float gr = fmaf(cur, wih_r, bih_r) + ghs[u];
                float gz = fmaf(cur, wih_z, bih_z) + ghs[u + 128];
                float gn = fmaf(cur, wih_n, bih_n);
                float r  = __fdividef(1.0f, 1.0f + __expf(-gr));
                float z  = __fdividef(1.0f, 1.0f + __expf(-gz));
                float na = fmaf(r, ghs[u + 256], gn);
                float e2 = __expf(2.0f * na);
                float n  = 1.0f - __fdividef(2.0f, e2 + 1.0f);
                float hnew = fmaf(z, h0 - n, n);
                h0 = hnew;
                hs[u] = hnew;
                if (u == 0) {
                    newin[t * BATCH + b0] = cur;
                    if (t > 0) pred[(size_t)b0 * (T_STEPS - 1) + (t - 1)] = xh0;
                }
                BAR_ARRIVE(2);                   // h(b0,t) published
                // x_hat partial for step t+1, batch 0 (hidden under rows' gh(b1,t))
                float p = hnew * wfc;
                #pragma unroll
                for (int off = 16; off >= 1; off >>= 1)
                    p += __shfl_xor_sync(0xffffffffu, p, off);
                if (lane == 0) xpart[wrp] = p;
            }
            BAR_SYNC(3);                         // gh(b1,t) ready
            // ---- batch b1 ----
            {
                float cur = (t == 0) ? x1 : ((x1 == 128.0f) ? xh1 : x1);
                const float* gh = ghs + GH_STRIDE;
                float gr = fmaf(cur, wih_r, bih_r) + gh[u];
                float gz = fmaf(cur, wih_z, bih_z) + gh[u + 128];
                float gn = fmaf(cur, wih_n, bih_n);
                float r  = __fdividef(1.0f, 1.0f + __expf(-gr));
                float z  = __fdividef(1.0f, 1.0f + __expf(-gz));
                float na = fmaf(r, gh[u + 256], gn);
                float e2 = __expf(2.0f * na);
                float n  = 1.0f - __fdividef(2.0f, e2 + 1.0f);
                float hnew = fmaf(z, h1 - n, n);
                h1 = hnew;
                hs[HID + u] = hnew;
                if (u == 0) {
                    newin[t * BATCH + b0 + 1] = cur;
                    if (t > 0) pred[(size_t)(b0 + 1) * (T_STEPS - 1) + (t - 1)] = xh1;
                }
                BAR_ARRIVE(4);                   // h(b1,t) published
                float p = hnew * wfc;
                #pragma unroll
                for (int off = 16; off >= 1; off >>= 1)
                    p += __shfl_xor_sync(0xffffffffu, p, off);
                if (lane == 0) xpart[4 + wrp] = p;
            }
        }
    }
}

extern "C" void kernel_launch(void* const* d_in, const int* in_sizes, int n_in,
                              void* d_out, int out_size)
{
    (void)in_sizes; (void)n_in; (void)out_size;
    const float* x    = (const float*)d_in[0];
    const float* Wih  = (const float*)d_in[1];
    const float* Whh  = (const float*)d_in[2];
    const float* bih  = (const float*)d_in[3];
    const float* bhh  = (const float*)d_in[4];
    const float* Wfc  = (const float*)d_in[5];
    const float* bfc  = (const float*)d_in[6];
    float* out = (float*)d_out;

    const size_t smem = (size_t)(NROW * WPAD2 + 2 * GH_STRIDE + 2 * HID + 8) * sizeof(float);
    cudaFuncSetAttribute(gru_impute_kernel, cudaFuncAttributeMaxDynamicSharedMemorySize, (int)smem);

    gru_impute_kernel<<<BATCH / 2, NTHREADS, smem>>>(x, Wih, Whh, bih, bhh, Wfc, bfc, out);
}

// round 7
// speedup vs baseline: 1.6091x; 1.6091x over previous
#include <cuda_runtime.h>

#define T_STEPS 2048
#define BATCH   256
#define HID     128
#define G3      384
#define NTHREADS 512
#define GHS     392      // ghs row stride
#define HSW     144      // swizzled h stride per batch: 128 + 4 pads

typedef unsigned long long u64;

__device__ __forceinline__ u64 ffma2(u64 a, u64 b, u64 c) {
    u64 d;
    asm("fma.rn.f32x2 %0, %1, %2, %3;" : "=l"(d) : "l"(a), "l"(b), "l"(c));
    return d;
}
__device__ __forceinline__ float hsum2(u64 v) {
    float x, y;
    asm("mov.b64 {%0, %1}, %2;" : "=f"(x), "=f"(y) : "l"(v));
    return x + y;
}

__global__ void __launch_bounds__(NTHREADS, 1)
gru_impute_kernel(const float* __restrict__ x,     // [B, T] (I=1)
                  const float* __restrict__ Wih,   // [384, 1]
                  const float* __restrict__ Whh,   // [384, 128]
                  const float* __restrict__ bih,   // [384]
                  const float* __restrict__ bhh,   // [384]
                  const float* __restrict__ Wfc,   // [1, 128]
                  const float* __restrict__ bfc,   // [1]
                  float* __restrict__ out)
{
    extern __shared__ float sm[];
    float* hsw   = sm;                 // 2 * HSW swizzled hidden state
    float* ghs   = sm + 2 * HSW;       // 2 * GHS gate pre-acts
    float* xpart = ghs + 2 * GHS;      // 8 x_hat warp partials

    const int tid  = threadIdx.x;
    const int lane = tid & 31;
    const int wrp  = tid >> 5;         // 0..15
    const int ks   = lane & 3;         // k-slice 0..3 (32 k's each)
    const int g    = lane >> 2;        // row-in-group 0..7
    const int b0   = blockIdx.x * 2;

    // ---- one-time staging: weights + bias into registers ----
    // warp wrp owns rows [wrp*24, wrp*24+24), 3 groups of 8; this lane's rows:
    // row_j = wrp*24 + j*8 + g, k-slice [32*ks, 32*ks+32)
    u64 wr0[16], wr1[16], wr2[16];
    float bh0, bh1, bh2;
    {
        const int r0 = wrp * 24 + g;
        const u64* p0 = reinterpret_cast<const u64*>(Whh + (r0     ) * HID + ks * 32);
        const u64* p1 = reinterpret_cast<const u64*>(Whh + (r0 +  8) * HID + ks * 32);
        const u64* p2 = reinterpret_cast<const u64*>(Whh + (r0 + 16) * HID + ks * 32);
        #pragma unroll
        for (int i = 0; i < 16; ++i) { wr0[i] = __ldg(p0 + i); wr1[i] = __ldg(p1 + i); wr2[i] = __ldg(p2 + i); }
        bh0 = bhh[r0]; bh1 = bhh[r0 + 8]; bh2 = bhh[r0 + 16];
    }

    for (int idx = tid; idx < 2 * HSW; idx += NTHREADS) hsw[idx] = 0.0f;
    if (tid < 8) xpart[tid] = 0.0f;

    // phase-B per-thread constants (threads 0..255)
    float wih_r = 0.f, wih_z = 0.f, wih_n = 0.f, bih_r = 0.f, bih_z = 0.f, bih_n = 0.f;
    float wfc = 0.f, bf = 0.f, xn = 0.f;
    const int u = tid & 127;
    const int b = tid >> 7;            // 0 or 1 for tid<256
    if (tid < 256) {
        wih_r = Wih[u];        bih_r = bih[u];
        wih_z = Wih[u + 128];  bih_z = bih[u + 128];
        wih_n = Wih[u + 256];  bih_n = bih[u + 256];
        wfc   = Wfc[u];
        bf    = bfc[0];
        xn    = __ldg(x + (size_t)(b0 + b) * T_STEPS);   // x at t=0
    }
    __syncthreads();

    float* newin = out;                       // [T, B]
    float* pred  = out + T_STEPS * BATCH;     // [B, T-1]

    const ulonglong2* hb0 = reinterpret_cast<const ulonglong2*>(hsw + ks * 36);
    const ulonglong2* hb1 = reinterpret_cast<const ulonglong2*>(hsw + HSW + ks * 36);

    for (int t = 0; t < T_STEPS; ++t) {
        // ================= Phase A: matvec, all 16 warps =================
        u64 a00 = 0ull, a01 = 0ull, a02 = 0ull;   // batch 0, rows j=0,1,2
        u64 a10 = 0ull, a11 = 0ull, a12 = 0ull;   // batch 1
        #pragma unroll
        for (int c = 0; c < 8; ++c) {             // 8 LDS.128 per batch
            ulonglong2 hv = hb0[c];
            a00 = ffma2(wr0[2 * c],     hv.x, a00);
            a01 = ffma2(wr1[2 * c],     hv.x, a01);
            a02 = ffma2(wr2[2 * c],     hv.x, a02);
            a00 = ffma2(wr0[2 * c + 1], hv.y, a00);
            a01 = ffma2(wr1[2 * c + 1], hv.y, a01);
            a02 = ffma2(wr2[2 * c + 1], hv.y, a02);
        }
        #pragma unroll
        for (int c = 0; c < 8; ++c) {
            ulonglong2 hv = hb1[c];
            a10 = ffma2(wr0[2 * c],     hv.x, a10);
            a11 = ffma2(wr1[2 * c],     hv.x, a11);
            a12 = ffma2(wr2[2 * c],     hv.x, a12);
            a10 = ffma2(wr0[2 * c + 1], hv.y, a10);
            a11 = ffma2(wr1[2 * c + 1], hv.y, a11);
            a12 = ffma2(wr2[2 * c + 1], hv.y, a12);
        }
        float f0 = hsum2(a00), f1 = hsum2(a01), f2 = hsum2(a02);
        float f3 = hsum2(a10), f4 = hsum2(a11), f5 = hsum2(a12);
        // reduce across the 4 k-slices (lanes ks=0..3 within each quad)
        f0 += __shfl_xor_sync(0xffffffffu, f0, 1); f0 += __shfl_xor_sync(0xffffffffu, f0, 2);
        f1 += __shfl_xor_sync(0xffffffffu, f1, 1); f1 += __shfl_xor_sync(0xffffffffu, f1, 2);
        f2 += __shfl_xor_sync(0xffffffffu, f2, 1); f2 += __shfl_xor_sync(0xffffffffu, f2, 2);
        f3 += __shfl_xor_sync(0xffffffffu, f3, 1); f3 += __shfl_xor_sync(0xffffffffu, f3, 2);
        f4 += __shfl_xor_sync(0xffffffffu, f4, 1); f4 += __shfl_xor_sync(0xffffffffu, f4, 2);
        f5 += __shfl_xor_sync(0xffffffffu, f5, 1); f5 += __shfl_xor_sync(0xffffffffu, f5, 2);
        if (ks == 0) {
            const int r0 = wrp * 24 + g;
            ghs[r0]            = f0 + bh0;
            ghs[r0 + 8]        = f1 + bh1;
            ghs[r0 + 16]       = f2 + bh2;
            ghs[GHS + r0]      = f3 + bh0;
            ghs[GHS + r0 + 8]  = f4 + bh1;
            ghs[GHS + r0 + 16] = f5 + bh2;
        }
        __syncthreads();

        // ================= Phase B: gates + update, threads 0..255 =================
        if (tid < 256) {
            float xh = xpart[b * 4] + xpart[b * 4 + 1] + xpart[b * 4 + 2] + xpart[b * 4 + 3] + bf;
            float xt = xn;
            if (t + 1 < T_STEPS)
                xn = __ldg(x + (size_t)(b0 + b) * T_STEPS + t + 1);

            const float* gh = ghs + b * GHS;
            float cur = (t == 0) ? xt : ((xt == 128.0f) ? xh : xt);

            float gr = fmaf(cur, wih_r, bih_r) + gh[u];
            float gz = fmaf(cur, wih_z, bih_z) + gh[u + 128];
            float gn = fmaf(cur, wih_n, bih_n);

            float r  = __fdividef(1.0f, 1.0f + __expf(-gr));
            float z  = __fdividef(1.0f, 1.0f + __expf(-gz));
            float na = fmaf(r, gh[u + 256], gn);
            float e2 = __expf(2.0f * na);
            float n  = 1.0f - __fdividef(2.0f, e2 + 1.0f);   // tanh

            const int hidx = b * HSW + u + (u >> 5) * 4;     // swizzled
            float hold = hsw[hidx];
            float hnew = fmaf(z, hold - n, n);
            hsw[hidx] = hnew;

            if (u == 0) {
                newin[t * BATCH + b0 + b] = cur;
                if (t > 0) pred[(size_t)(b0 + b) * (T_STEPS - 1) + (t - 1)] = xh;
            }
            // x_hat partial for step t+1 (consumed next iteration)
            float p = hnew * wfc;
            #pragma unroll
            for (int off = 16; off >= 1; off >>= 1)
                p += __shfl_xor_sync(0xffffffffu, p, off);
            if (lane == 0) xpart[b * 4 + ((tid >> 5) & 3)] = p;
        }
        __syncthreads();
    }
}

extern "C" void kernel_launch(void* const* d_in, const int* in_sizes, int n_in,
                              void* d_out, int out_size)
{
    (void)in_sizes; (void)n_in; (void)out_size;
    const float* x    = (const float*)d_in[0];
    const float* Wih  = (const float*)d_in[1];
    const float* Whh  = (const float*)d_in[2];
    const float* bih  = (const float*)d_in[3];
    const float* bhh  = (const float*)d_in[4];
    const float* Wfc  = (const float*)d_in[5];
    const float* bfc  = (const float*)d_in[6];
    float* out = (float*)d_out;

    const size_t smem = (size_t)(2 * HSW + 2 * GHS + 8) * sizeof(float);
    cudaFuncSetAttribute(gru_impute_kernel, cudaFuncAttributeMaxDynamicSharedMemorySize, (int)smem);

    gru_impute_kernel<<<BATCH / 2, NTHREADS, smem>>>(x, Wih, Whh, bih, bhh, Wfc, bfc, out);
}